// round 10
// baseline (speedup 1.0000x reference)
#include <cuda_runtime.h>
#include <cuda_fp16.h>
#include <math.h>

#define N_NODES 200000
#define N_HE    100000
#define NNZ     1000000
#define N_MACRO 512
#define CC      64
#define SLOPE   0.1f

#define NBN 49   // ceil(200000/4096)
#define NBE 25   // ceil(100000/4096)

#define FUSE_GRID 1563   // ceil(200000/128)

// ---------------- device scratch ----------------
__device__ float g_xl[N_NODES * CC];
__device__ float g_s1[N_NODES];
__device__ float g_efeat[N_HE * CC];
__device__ float g_s2[N_HE];
__device__ int   g_mcount[N_NODES];
__device__ int   g_deg_n[N_NODES];
__device__ int   g_deg_e[N_HE];
__device__ int   g_rs_n[N_NODES + 1];
__device__ int   g_rs_e[N_HE + 1];
__device__ int   g_cur_n[N_NODES];
__device__ int   g_cur_e[N_HE];
__device__ int   g_bsum[NBN + NBE];
__device__ int   g_pn_he[NNZ];
__device__ int   g_pe_node[NNZ];
__device__ int   g_pe_pin[NNZ];
__device__ __half g_whh[64 * 256];   // Wpost^T fp16 hi: [n][k]
__device__ __half g_whl[64 * 256];   // Wpost^T fp16 lo
__device__ float g_pool_all[CC];
__device__ float g_pool_macro[CC];

__device__ __forceinline__ float lrelu(float v) { return v >= 0.f ? v : SLOPE * v; }

__device__ __forceinline__ float warpMax(float v) {
#pragma unroll
    for (int o = 16; o > 0; o >>= 1) v = fmaxf(v, __shfl_xor_sync(0xffffffffu, v, o));
    return v;
}
__device__ __forceinline__ float warpSum(float v) {
#pragma unroll
    for (int o = 16; o > 0; o >>= 1) v += __shfl_xor_sync(0xffffffffu, v, o);
    return v;
}
__device__ __forceinline__ int warpSumI(int v) {
#pragma unroll
    for (int o = 16; o > 0; o >>= 1) v += __shfl_xor_sync(0xffffffffu, v, o);
    return v;
}
__device__ __forceinline__ unsigned smem_u32(const void* p) {
    unsigned a;
    asm("{ .reg .u64 t; cvta.to.shared.u64 t, %1; cvt.u32.u64 %0, t; }" : "=r"(a) : "l"(p));
    return a;
}
__device__ __forceinline__ void split2(float vx, float vy, __half2& hi, __half2& lo) {
    __half hx = __float2half_rn(vx), hy = __float2half_rn(vy);
    __half lx = __float2half_rn(vx - __half2float(hx));
    __half ly = __float2half_rn(vy - __half2float(hy));
    hi = __halves2half2(hx, hy);
    lo = __halves2half2(lx, ly);
}

// ---------------- init / CSR build ----------------
__global__ void k_init() {
    int i = blockIdx.x * blockDim.x + threadIdx.x;
    int st = gridDim.x * blockDim.x;
    for (int j = i; j < N_NODES; j += st) { g_deg_n[j] = 0; g_cur_n[j] = 0; g_mcount[j] = 0; }
    for (int j = i; j < N_HE; j += st)    { g_deg_e[j] = 0; g_cur_e[j] = 0; }
    if (i < CC) { g_pool_all[i] = 0.f; g_pool_macro[i] = 0.f; }
}

// Wpost [256 k][64 n] fp32 -> g_whh/g_whl [64 n][256 k] fp16 split (transposed)
__global__ void k_prep(const float* __restrict__ Wpost) {
    int i = blockIdx.x * blockDim.x + threadIdx.x;   // i = n*256 + k
    if (i < 64 * 256) {
        int n = i >> 8, k = i & 255;
        float w = Wpost[k * 64 + n];
        __half h = __float2half_rn(w);
        g_whh[i] = h;
        g_whl[i] = __float2half_rn(w - __half2float(h));
    }
}

__global__ void k_ismacro(const int* __restrict__ mi) {
    int i = blockIdx.x * blockDim.x + threadIdx.x;
    if (i < N_MACRO) atomicAdd(&g_mcount[mi[i]], 1);
}

__global__ void k_deg(const int* __restrict__ ei) {
    int p = blockIdx.x * blockDim.x + threadIdx.x;
    if (p < NNZ) {
        atomicAdd(&g_deg_n[ei[p]], 1);
        atomicAdd(&g_deg_e[ei[NNZ + p]], 1);
    }
}

// ----- 3-phase multi-block exclusive scan -----
__global__ void k_scan1() {
    int blk = blockIdx.x;
    const int* deg; int base; int n;
    if (blk < NBN) { deg = g_deg_n; base = blk * 4096; n = N_NODES; }
    else           { deg = g_deg_e; base = (blk - NBN) * 4096; n = N_HE; }
    int t = threadIdx.x;
    int i = base + t * 4;
    int s = 0;
    if (i + 3 < n) {
        int4 v = *(const int4*)&deg[i];
        s = v.x + v.y + v.z + v.w;
    } else {
        for (int j = 0; j < 4; j++) if (i + j < n) s += deg[i + j];
    }
    s = warpSumI(s);
    __shared__ int sh[32];
    int lane = t & 31, w = t >> 5;
    if (lane == 0) sh[w] = s;
    __syncthreads();
    if (w == 0) {
        int v = sh[lane];
        v = warpSumI(v);
        if (lane == 0) g_bsum[blk] = v;
    }
}

__global__ void k_scan2() {
    int t = threadIdx.x;
    if (t == 0) {
        int run = 0;
        for (int b = 0; b < NBN; b++) { int v = g_bsum[b]; g_bsum[b] = run; run += v; }
        g_rs_n[N_NODES] = NNZ;
    }
    if (t == 32) {
        int run = 0;
        for (int b = NBN; b < NBN + NBE; b++) { int v = g_bsum[b]; g_bsum[b] = run; run += v; }
        g_rs_e[N_HE] = NNZ;
    }
}

__global__ void k_scan3() {
    int blk = blockIdx.x;
    const int* deg; int* rs; int base; int n;
    if (blk < NBN) { deg = g_deg_n; rs = g_rs_n; base = blk * 4096; n = N_NODES; }
    else           { deg = g_deg_e; rs = g_rs_e; base = (blk - NBN) * 4096; n = N_HE; }
    int t = threadIdx.x;
    int lane = t & 31, w = t >> 5;
    int i = base + t * 4;
    int d0 = 0, d1 = 0, d2 = 0, d3 = 0;
    if (i + 3 < n) {
        int4 v = *(const int4*)&deg[i];
        d0 = v.x; d1 = v.y; d2 = v.z; d3 = v.w;
    } else {
        if (i + 0 < n) d0 = deg[i + 0];
        if (i + 1 < n) d1 = deg[i + 1];
        if (i + 2 < n) d2 = deg[i + 2];
        if (i + 3 < n) d3 = deg[i + 3];
    }
    int e1 = d0, e2 = d0 + d1, e3 = d0 + d1 + d2;
    int tsum = e3 + d3;
    int x = tsum;
#pragma unroll
    for (int o = 1; o < 32; o <<= 1) {
        int v = __shfl_up_sync(0xffffffffu, x, o);
        if (lane >= o) x += v;
    }
    __shared__ int sh[32];
    if (lane == 31) sh[w] = x;
    __syncthreads();
    if (w == 0) {
        int y = sh[lane];
#pragma unroll
        for (int o = 1; o < 32; o <<= 1) {
            int v = __shfl_up_sync(0xffffffffu, y, o);
            if (lane >= o) y += v;
        }
        sh[lane] = y;
    }
    __syncthreads();
    int off = g_bsum[blk] + (x - tsum) + (w > 0 ? sh[w - 1] : 0);
    if (i + 0 < n) rs[i + 0] = off;
    if (i + 1 < n) rs[i + 1] = off + e1;
    if (i + 2 < n) rs[i + 2] = off + e2;
    if (i + 3 < n) rs[i + 3] = off + e3;
}

__global__ void k_scatter(const int* __restrict__ ei) {
    int p = blockIdx.x * blockDim.x + threadIdx.x;
    if (p < NNZ) {
        int node = ei[p], he = ei[NNZ + p];
        int pos = atomicAdd(&g_cur_n[node], 1);
        g_pn_he[g_rs_n[node] + pos] = he;
        int pos2 = atomicAdd(&g_cur_e[he], 1);
        int slot = g_rs_e[he] + pos2;
        g_pe_node[slot] = node;
        g_pe_pin[slot] = p;
    }
}

// ---------------- xl = h @ W1 + b1 ; s1 = xl . att[:64]  (warp per node) ----------------
__global__ void k_xl(const float* __restrict__ x, const float* __restrict__ fp,
                     const float* __restrict__ W1, const float* __restrict__ b1,
                     const float* __restrict__ att) {
    __shared__ float sW1[32 * 64];
    int tid = threadIdx.x;
    for (int v = tid; v < 32 * 64; v += 256) sW1[v] = W1[v];
    __syncthreads();
    int wid = tid >> 5, lane = tid & 31;
    int node = blockIdx.x * 8 + wid;
    float h;
    if (lane < 29)        h = x[node * 29 + lane];
    else if (lane == 29)  h = fp[node * 2 + 0];
    else if (lane == 30)  h = fp[node * 2 + 1];
    else                  h = (g_mcount[node] > 0) ? 1.f : 0.f;
    float a0 = b1[lane], a1 = b1[lane + 32];
#pragma unroll
    for (int k = 0; k < 32; k++) {
        float hk = __shfl_sync(0xffffffffu, h, k);
        a0 += hk * sW1[k * 64 + lane];
        a1 += hk * sW1[k * 64 + lane + 32];
    }
    g_xl[node * 64 + lane] = a0;
    g_xl[node * 64 + lane + 32] = a1;
    float p = a0 * att[lane] + a1 * att[lane + 32];
    p = warpSum(p);
    if (lane == 0) g_s1[node] = p;
}

// ---------------- hyperedge aggregation (warp per he) ----------------
__global__ void k_he(const float* __restrict__ pinf, const float* __restrict__ Wpin,
                     const float* __restrict__ att) {
    __shared__ float sWpin[4 * 64];
    int tid = threadIdx.x;
    for (int v = tid; v < 256; v += 256) sWpin[v] = Wpin[v];
    __syncthreads();
    int wid = tid >> 5, lane = tid & 31;
    int he = blockIdx.x * 8 + wid;
    int start = g_rs_e[he], end = g_rs_e[he + 1];
    int c0 = lane * 2;
    float acc0 = 0.f, acc1 = 0.f;
    float4 pfs = make_float4(0.f, 0.f, 0.f, 0.f);
    for (int s = start; s < end; s++) {
        int node = g_pe_node[s];
        int pin = g_pe_pin[s];
        float4 pf = *(const float4*)&pinf[pin * 4];   // broadcast across warp
        float2 xv = *(const float2*)&g_xl[node * 64 + c0];
        acc0 += xv.x; acc1 += xv.y;
        pfs.x += pf.x; pfs.y += pf.y; pfs.z += pf.z; pfs.w += pf.w;
    }
    acc0 += pfs.x * sWpin[c0]       + pfs.y * sWpin[64 + c0]
          + pfs.z * sWpin[128 + c0] + pfs.w * sWpin[192 + c0];
    acc1 += pfs.x * sWpin[c0 + 1]       + pfs.y * sWpin[64 + c0 + 1]
          + pfs.z * sWpin[128 + c0 + 1] + pfs.w * sWpin[192 + c0 + 1];
    int deg = end - start;
    float inv = 1.f / fmaxf((float)deg, 1.f);
    float e0 = acc0 * inv, e1 = acc1 * inv;
    *(float2*)&g_efeat[he * 64 + c0] = make_float2(e0, e1);
    float p = e0 * att[64 + c0] + e1 * att[64 + c0 + 1];
    p = warpSum(p);
    if (lane == 0) g_s2[he] = p;
}

// ---------------- fused: node PNA -> smem split-fp16 -> MMA -> pools ----------------
#define ASTR 264
#define BSTR 264
#define FUSE_SMEM ((128 * ASTR * 2 + 64 * BSTR * 2) * 2 + 256)

__global__ __launch_bounds__(256, 1) void k_npna(const float* __restrict__ bpost) {
    extern __shared__ char smraw[];
    __half* sAh = (__half*)smraw;
    __half* sAl = sAh + 128 * ASTR;
    __half* sBh = sAl + 128 * ASTR;
    __half* sBl = sBh + 64 * BSTR;
    float* pool = (float*)(sBl + 64 * BSTR);
    int tid = threadIdx.x, wid = tid >> 5, lane = tid & 31;
    int node0 = blockIdx.x * 128;
    if (tid < 64) pool[tid] = 0.f;

    // load B split (Wpost^T fp16 hi/lo)
    {
        int n = tid >> 2, q = (tid & 3) * 64;
        const __half* srch = &g_whh[n * 256 + q];
        const __half* srcl = &g_whl[n * 256 + q];
        __half* dsth = &sBh[n * BSTR + q];
        __half* dstl = &sBl[n * BSTR + q];
#pragma unroll
        for (int i2 = 0; i2 < 8; i2++) {
            *(uint4*)&dsth[i2 * 8] = *(const uint4*)&srch[i2 * 8];
            *(uint4*)&dstl[i2 * 8] = *(const uint4*)&srcl[i2 * 8];
        }
    }

    int c0 = lane * 2;
    // phase 1: each warp computes PNA for 16 nodes, writes split fp16 rows to smem
    for (int i = 0; i < 16; i++) {
        int row = wid * 16 + i;
        int node = node0 + row;
        unsigned arow = (unsigned)(row * ASTR + c0);
        if (node >= N_NODES) {
            __half2 z = __floats2half2_rn(0.f, 0.f);
            *(__half2*)&sAh[arow] = z;        *(__half2*)&sAl[arow] = z;
            *(__half2*)&sAh[arow + 64] = z;   *(__half2*)&sAl[arow + 64] = z;
            *(__half2*)&sAh[arow + 128] = z;  *(__half2*)&sAl[arow + 128] = z;
            *(__half2*)&sAh[arow + 192] = z;  *(__half2*)&sAl[arow + 192] = z;
            continue;
        }
        int start = g_rs_n[node];
        int deg = g_rs_n[node + 1] - start;
        if (deg == 0) {
            __half2 z = __floats2half2_rn(0.f, 0.f);
            __half2 e, el;
            split2(1e-6f, 1e-6f, e, el);
            *(__half2*)&sAh[arow] = z;        *(__half2*)&sAl[arow] = z;
            *(__half2*)&sAh[arow + 64] = z;   *(__half2*)&sAl[arow + 64] = z;
            *(__half2*)&sAh[arow + 128] = z;  *(__half2*)&sAl[arow + 128] = z;
            *(__half2*)&sAh[arow + 192] = e;  *(__half2*)&sAl[arow + 192] = el;
            continue;
        }
        float s1n = g_s1[node];
        float2 sum = make_float2(0.f, 0.f), sq = make_float2(0.f, 0.f);
        float2 vmx = make_float2(-INFINITY, -INFINITY);
        float2 vmn = make_float2(INFINITY, INFINITY);
        if (deg <= 32) {
            int he_l = 0; float a = -INFINITY;
            if (lane < deg) { he_l = g_pn_he[start + lane]; a = lrelu(s1n + g_s2[he_l]); }
            float m = warpMax(a);
            float ex = (lane < deg) ? expf(a - m) : 0.f;
            float den = warpSum(ex);
            float invden = 1.f / (den + 1e-16f);
            for (int j0 = 0; j0 < deg; j0 += 8) {
                int jn = deg - j0; if (jn > 8) jn = 8;
                float2 egb[8]; float alp[8];
#pragma unroll
                for (int u = 0; u < 8; u++) {
                    if (u < jn) {
                        int hej = __shfl_sync(0xffffffffu, he_l, j0 + u);
                        alp[u] = __shfl_sync(0xffffffffu, ex, j0 + u) * invden;
                        egb[u] = *(const float2*)&g_efeat[hej * 64 + c0];
                    }
                }
#pragma unroll
                for (int u = 0; u < 8; u++) {
                    if (u < jn) {
                        float m0 = egb[u].x * alp[u], m1 = egb[u].y * alp[u];
                        sum.x += m0; sum.y += m1;
                        sq.x += m0 * m0; sq.y += m1 * m1;
                        vmx.x = fmaxf(vmx.x, m0); vmx.y = fmaxf(vmx.y, m1);
                        vmn.x = fminf(vmn.x, m0); vmn.y = fminf(vmn.y, m1);
                    }
                }
            }
        } else {
            float lm = -INFINITY;
            for (int j = lane; j < deg; j += 32) {
                int he = g_pn_he[start + j];
                lm = fmaxf(lm, lrelu(s1n + g_s2[he]));
            }
            float m = warpMax(lm);
            float ls = 0.f;
            for (int j = lane; j < deg; j += 32) {
                int he = g_pn_he[start + j];
                ls += expf(lrelu(s1n + g_s2[he]) - m);
            }
            float den = warpSum(ls);
            float invden = 1.f / (den + 1e-16f);
            for (int j = 0; j < deg; j++) {
                int he = g_pn_he[start + j];
                float alpha = expf(lrelu(s1n + g_s2[he]) - m) * invden;
                float2 eg = *(const float2*)&g_efeat[he * 64 + c0];
                float m0 = eg.x * alpha, m1 = eg.y * alpha;
                sum.x += m0; sum.y += m1;
                sq.x += m0 * m0; sq.y += m1 * m1;
                vmx.x = fmaxf(vmx.x, m0); vmx.y = fmaxf(vmx.y, m1);
                vmn.x = fminf(vmn.x, m0); vmn.y = fminf(vmn.y, m1);
            }
        }
        float invd = 1.f / (float)deg;
        float2 mean = make_float2(sum.x * invd, sum.y * invd);
        float2 msq  = make_float2(sq.x * invd, sq.y * invd);
        float2 stdv = make_float2(sqrtf(fmaxf(msq.x - mean.x * mean.x, 0.f) + 1e-12f),
                                  sqrtf(fmaxf(msq.y - mean.y * mean.y, 0.f) + 1e-12f));
        __half2 h, l;
        split2(mean.x, mean.y, h, l);
        *(__half2*)&sAh[arow] = h;        *(__half2*)&sAl[arow] = l;
        split2(vmx.x, vmx.y, h, l);
        *(__half2*)&sAh[arow + 64] = h;   *(__half2*)&sAl[arow + 64] = l;
        split2(vmn.x, vmn.y, h, l);
        *(__half2*)&sAh[arow + 128] = h;  *(__half2*)&sAl[arow + 128] = l;
        split2(stdv.x, stdv.y, h, l);
        *(__half2*)&sAh[arow + 192] = h;  *(__half2*)&sAl[arow + 192] = l;
    }
    __syncthreads();

    // phase 2: split-fp16 MMA  D = Ahi*Bhi + Ahi*Blo + Alo*Bhi
    int r0 = wid * 16;
    int g = lane >> 2, t4 = lane & 3;
    float acc[8][4];
#pragma unroll
    for (int i = 0; i < 8; i++)
#pragma unroll
        for (int j = 0; j < 4; j++) acc[i][j] = 0.f;

    unsigned aRow = (unsigned)((r0 + (lane & 15)) * ASTR + ((lane >> 4) << 3));
    unsigned aHiBase = smem_u32(sAh) + aRow * 2u;
    unsigned aLoBase = smem_u32(sAl) + aRow * 2u;
    unsigned bHiBase = smem_u32(sBh);
    unsigned bLoBase = smem_u32(sBl);

#pragma unroll
    for (int ks = 0; ks < 16; ks++) {
        int k0 = ks * 16;
        unsigned ah0, ah1, ah2, ah3, al0, al1, al2, al3;
        asm volatile("ldmatrix.sync.aligned.m8n8.x4.shared.b16 {%0,%1,%2,%3}, [%4];"
                     : "=r"(ah0), "=r"(ah1), "=r"(ah2), "=r"(ah3)
                     : "r"(aHiBase + (unsigned)(k0 * 2)));
        asm volatile("ldmatrix.sync.aligned.m8n8.x4.shared.b16 {%0,%1,%2,%3}, [%4];"
                     : "=r"(al0), "=r"(al1), "=r"(al2), "=r"(al3)
                     : "r"(aLoBase + (unsigned)(k0 * 2)));
#pragma unroll
        for (int nt = 0; nt < 8; nt++) {
            unsigned boff = (unsigned)(((nt * 8 + g) * BSTR + k0 + t4 * 2) * 2);
            unsigned bh0, bh1, bl0, bl1;
            asm volatile("ld.shared.b32 %0, [%1];" : "=r"(bh0) : "r"(bHiBase + boff));
            asm volatile("ld.shared.b32 %0, [%1];" : "=r"(bh1) : "r"(bHiBase + boff + 16u));
            asm volatile("ld.shared.b32 %0, [%1];" : "=r"(bl0) : "r"(bLoBase + boff));
            asm volatile("ld.shared.b32 %0, [%1];" : "=r"(bl1) : "r"(bLoBase + boff + 16u));
            asm volatile(
                "mma.sync.aligned.m16n8k16.row.col.f32.f16.f16.f32 "
                "{%0,%1,%2,%3}, {%4,%5,%6,%7}, {%8,%9}, {%0,%1,%2,%3};"
                : "+f"(acc[nt][0]), "+f"(acc[nt][1]), "+f"(acc[nt][2]), "+f"(acc[nt][3])
                : "r"(ah0), "r"(ah1), "r"(ah2), "r"(ah3), "r"(bh0), "r"(bh1));
            asm volatile(
                "mma.sync.aligned.m16n8k16.row.col.f32.f16.f16.f32 "
                "{%0,%1,%2,%3}, {%4,%5,%6,%7}, {%8,%9}, {%0,%1,%2,%3};"
                : "+f"(acc[nt][0]), "+f"(acc[nt][1]), "+f"(acc[nt][2]), "+f"(acc[nt][3])
                : "r"(ah0), "r"(ah1), "r"(ah2), "r"(ah3), "r"(bl0), "r"(bl1));
            asm volatile(
                "mma.sync.aligned.m16n8k16.row.col.f32.f16.f16.f32 "
                "{%0,%1,%2,%3}, {%4,%5,%6,%7}, {%8,%9}, {%0,%1,%2,%3};"
                : "+f"(acc[nt][0]), "+f"(acc[nt][1]), "+f"(acc[nt][2]), "+f"(acc[nt][3])
                : "r"(al0), "r"(al1), "r"(al2), "r"(al3), "r"(bh0), "r"(bh1));
        }
    }

    // epilogue: bias + lrelu; accumulate mean-pool (smem) and macro-pool (global)
    int row0 = node0 + r0 + g, row1 = row0 + 8;
    bool v0 = row0 < N_NODES, v1 = row1 < N_NODES;
    int cnt0 = v0 ? g_mcount[row0] : 0;
    int cnt1 = v1 ? g_mcount[row1] : 0;
#pragma unroll
    for (int nt = 0; nt < 8; nt++) {
        int c = nt * 8 + t4 * 2;
        float2 bp = *(const float2*)&bpost[c];
        float h00 = lrelu(acc[nt][0] + bp.x), h01 = lrelu(acc[nt][1] + bp.y);
        float h10 = lrelu(acc[nt][2] + bp.x), h11 = lrelu(acc[nt][3] + bp.y);
        if (cnt0) {
            atomicAdd(&g_pool_macro[c], (float)cnt0 * h00);
            atomicAdd(&g_pool_macro[c + 1], (float)cnt0 * h01);
        }
        if (cnt1) {
            atomicAdd(&g_pool_macro[c], (float)cnt1 * h10);
            atomicAdd(&g_pool_macro[c + 1], (float)cnt1 * h11);
        }
        float s0 = (v0 ? h00 : 0.f) + (v1 ? h10 : 0.f);
        float s1 = (v0 ? h01 : 0.f) + (v1 ? h11 : 0.f);
#pragma unroll
        for (int o = 4; o < 32; o <<= 1) {
            s0 += __shfl_xor_sync(0xffffffffu, s0, o);
            s1 += __shfl_xor_sync(0xffffffffu, s1, o);
        }
        if (g == 0) {
            atomicAdd(&pool[c], s0);
            atomicAdd(&pool[c + 1], s1);
        }
    }
    __syncthreads();
    if (tid < 64) atomicAdd(&g_pool_all[tid], pool[tid]);
}

// ---------------- MLP head ----------------
__global__ void k_mlp(const float* __restrict__ Wm1, const float* __restrict__ bm1,
                      const float* __restrict__ Wm2, const float* __restrict__ bm2,
                      const float* __restrict__ Wm3, const float* __restrict__ bm3,
                      float* __restrict__ out) {
    int t = threadIdx.x;
    __shared__ float pooled[128];
    __shared__ float z1[64];
    __shared__ float z2[32];
    if (t < 64) {
        pooled[t] = g_pool_macro[t] * (1.f / (float)N_MACRO);
        pooled[t + 64] = g_pool_all[t] * (1.f / (float)N_NODES);
    }
    __syncthreads();
    if (t < 64) {
        float a = bm1[t];
        for (int k = 0; k < 128; k++) a += pooled[k] * Wm1[k * 64 + t];
        z1[t] = lrelu(a);
    }
    __syncthreads();
    if (t < 32) {
        float a = bm2[t];
        for (int k = 0; k < 64; k++) a += z1[k] * Wm2[k * 32 + t];
        z2[t] = lrelu(a);
    }
    __syncthreads();
    if (t < 32) {
        float p = z2[t] * Wm3[t];
        p = warpSum(p);
        if (t == 0) out[0] = p + bm3[0];
    }
}

// ---------------- launch ----------------
extern "C" void kernel_launch(void* const* d_in, const int* in_sizes, int n_in,
                              void* d_out, int out_size) {
    const float* x     = (const float*)d_in[0];
    const float* fp    = (const float*)d_in[1];
    const int*   ei    = (const int*)d_in[2];
    const float* pinf  = (const float*)d_in[3];
    const int*   mi    = (const int*)d_in[4];
    const float* W1    = (const float*)d_in[5];
    const float* b1    = (const float*)d_in[6];
    const float* Wpin  = (const float*)d_in[7];
    const float* att   = (const float*)d_in[8];
    const float* Wpost = (const float*)d_in[9];
    const float* bpost = (const float*)d_in[10];
    const float* Wm1   = (const float*)d_in[11];
    const float* bm1   = (const float*)d_in[12];
    const float* Wm2   = (const float*)d_in[13];
    const float* bm2   = (const float*)d_in[14];
    const float* Wm3   = (const float*)d_in[15];
    const float* bm3   = (const float*)d_in[16];
    float* out = (float*)d_out;

    cudaFuncSetAttribute(k_npna, cudaFuncAttributeMaxDynamicSharedMemorySize, FUSE_SMEM);

    k_init<<<400, 256>>>();
    k_prep<<<64, 256>>>(Wpost);
    k_ismacro<<<2, 256>>>(mi);
    k_deg<<<(NNZ + 255) / 256, 256>>>(ei);
    k_scan1<<<NBN + NBE, 1024>>>();
    k_scan2<<<1, 64>>>();
    k_scan3<<<NBN + NBE, 1024>>>();
    k_scatter<<<(NNZ + 255) / 256, 256>>>(ei);
    k_xl<<<N_NODES / 8, 256>>>(x, fp, W1, b1, att);
    k_he<<<N_HE / 8, 256>>>(pinf, Wpin, att);
    k_npna<<<FUSE_GRID, 256, FUSE_SMEM>>>(bpost);
    k_mlp<<<1, 128>>>(Wm1, bm1, Wm2, bm2, Wm3, bm3, out);
}

// round 13
// speedup vs baseline: 1.1508x; 1.1508x over previous
#include <cuda_runtime.h>
#include <cuda_fp16.h>
#include <math.h>

#define N_NODES 200000
#define N_HE    100000
#define NNZ     1000000
#define N_MACRO 512
#define CC      64
#define SLOPE   0.1f

#define NBN 49   // ceil(200000/4096)
#define NBE 25   // ceil(100000/4096)

#define NN_PAD 200064          // 1563 * 128
#define MMA_GRID 1563

// ---------------- device scratch ----------------
__device__ float g_xl[N_NODES * CC];
__device__ float g_s1[N_NODES];
__device__ float g_efeat[N_HE * CC];
__device__ float g_s2[N_HE];
__device__ int   g_mcount[N_NODES];
__device__ int   g_deg_n[N_NODES];
__device__ int   g_deg_e[N_HE];
__device__ int   g_rs_n[N_NODES + 1];
__device__ int   g_rs_e[N_HE + 1];
__device__ int   g_cur_n[N_NODES];
__device__ int   g_cur_e[N_HE];
__device__ int   g_bsum[NBN + NBE];
__device__ int   g_pn_he[NNZ];
__device__ int   g_pe_node[NNZ];
__device__ int   g_pe_pin[NNZ];
__device__ __half g_pAhi[(size_t)NN_PAD * 256];   // 102.4 MB (pad rows stay 0)
__device__ __half g_pAlo[(size_t)NN_PAD * 256];   // 102.4 MB
__device__ __half g_whh[64 * 256];                // Wpost^T fp16 hi: [n][k]
__device__ __half g_whl[64 * 256];                // Wpost^T fp16 lo
__device__ float g_pool_all[CC];
__device__ float g_pool_macro[CC];

__device__ __forceinline__ float lrelu(float v) { return v >= 0.f ? v : SLOPE * v; }

__device__ __forceinline__ float warpMax(float v) {
#pragma unroll
    for (int o = 16; o > 0; o >>= 1) v = fmaxf(v, __shfl_xor_sync(0xffffffffu, v, o));
    return v;
}
__device__ __forceinline__ float warpSum(float v) {
#pragma unroll
    for (int o = 16; o > 0; o >>= 1) v += __shfl_xor_sync(0xffffffffu, v, o);
    return v;
}
__device__ __forceinline__ int warpSumI(int v) {
#pragma unroll
    for (int o = 16; o > 0; o >>= 1) v += __shfl_xor_sync(0xffffffffu, v, o);
    return v;
}
__device__ __forceinline__ unsigned smem_u32(const void* p) {
    unsigned a;
    asm("{ .reg .u64 t; cvta.to.shared.u64 t, %1; cvt.u32.u64 %0, t; }" : "=r"(a) : "l"(p));
    return a;
}
// split a float2 into fp16 hi pair + fp16 lo (residual) pair
__device__ __forceinline__ void split2(float vx, float vy, __half2& hi, __half2& lo) {
    __half hx = __float2half_rn(vx), hy = __float2half_rn(vy);
    __half lx = __float2half_rn(vx - __half2float(hx));
    __half ly = __float2half_rn(vy - __half2float(hy));
    hi = __halves2half2(hx, hy);
    lo = __halves2half2(lx, ly);
}

// ---------------- init / CSR build ----------------
__global__ void k_init() {
    int i = blockIdx.x * blockDim.x + threadIdx.x;
    int st = gridDim.x * blockDim.x;
    for (int j = i; j < N_NODES; j += st) { g_deg_n[j] = 0; g_cur_n[j] = 0; g_mcount[j] = 0; }
    for (int j = i; j < N_HE; j += st)    { g_deg_e[j] = 0; g_cur_e[j] = 0; }
    if (i < CC) { g_pool_all[i] = 0.f; g_pool_macro[i] = 0.f; }
}

// Wpost [256 k][64 n] fp32 -> g_whh/g_whl [64 n][256 k] fp16 split (transposed)
__global__ void k_prep(const float* __restrict__ Wpost) {
    int i = blockIdx.x * blockDim.x + threadIdx.x;   // i = n*256 + k
    if (i < 64 * 256) {
        int n = i >> 8, k = i & 255;
        float w = Wpost[k * 64 + n];
        __half h = __float2half_rn(w);
        g_whh[i] = h;
        g_whl[i] = __float2half_rn(w - __half2float(h));
    }
}

__global__ void k_ismacro(const int* __restrict__ mi) {
    int i = blockIdx.x * blockDim.x + threadIdx.x;
    if (i < N_MACRO) atomicAdd(&g_mcount[mi[i]], 1);
}

__global__ void k_deg(const int* __restrict__ ei) {
    int p = blockIdx.x * blockDim.x + threadIdx.x;
    if (p < NNZ) {
        atomicAdd(&g_deg_n[ei[p]], 1);
        atomicAdd(&g_deg_e[ei[NNZ + p]], 1);
    }
}

// ----- 3-phase multi-block exclusive scan -----
__global__ void k_scan1() {
    int blk = blockIdx.x;
    const int* deg; int base; int n;
    if (blk < NBN) { deg = g_deg_n; base = blk * 4096; n = N_NODES; }
    else           { deg = g_deg_e; base = (blk - NBN) * 4096; n = N_HE; }
    int t = threadIdx.x;
    int i = base + t * 4;
    int s = 0;
    if (i + 3 < n) {
        int4 v = *(const int4*)&deg[i];
        s = v.x + v.y + v.z + v.w;
    } else {
        for (int j = 0; j < 4; j++) if (i + j < n) s += deg[i + j];
    }
    s = warpSumI(s);
    __shared__ int sh[32];
    int lane = t & 31, w = t >> 5;
    if (lane == 0) sh[w] = s;
    __syncthreads();
    if (w == 0) {
        int v = sh[lane];
        v = warpSumI(v);
        if (lane == 0) g_bsum[blk] = v;
    }
}

__global__ void k_scan2() {
    int t = threadIdx.x;
    if (t == 0) {
        int run = 0;
        for (int b = 0; b < NBN; b++) { int v = g_bsum[b]; g_bsum[b] = run; run += v; }
        g_rs_n[N_NODES] = NNZ;
    }
    if (t == 32) {
        int run = 0;
        for (int b = NBN; b < NBN + NBE; b++) { int v = g_bsum[b]; g_bsum[b] = run; run += v; }
        g_rs_e[N_HE] = NNZ;
    }
}

__global__ void k_scan3() {
    int blk = blockIdx.x;
    const int* deg; int* rs; int base; int n;
    if (blk < NBN) { deg = g_deg_n; rs = g_rs_n; base = blk * 4096; n = N_NODES; }
    else           { deg = g_deg_e; rs = g_rs_e; base = (blk - NBN) * 4096; n = N_HE; }
    int t = threadIdx.x;
    int lane = t & 31, w = t >> 5;
    int i = base + t * 4;
    int d0 = 0, d1 = 0, d2 = 0, d3 = 0;
    if (i + 3 < n) {
        int4 v = *(const int4*)&deg[i];
        d0 = v.x; d1 = v.y; d2 = v.z; d3 = v.w;
    } else {
        if (i + 0 < n) d0 = deg[i + 0];
        if (i + 1 < n) d1 = deg[i + 1];
        if (i + 2 < n) d2 = deg[i + 2];
        if (i + 3 < n) d3 = deg[i + 3];
    }
    int e1 = d0, e2 = d0 + d1, e3 = d0 + d1 + d2;
    int tsum = e3 + d3;
    int x = tsum;
#pragma unroll
    for (int o = 1; o < 32; o <<= 1) {
        int v = __shfl_up_sync(0xffffffffu, x, o);
        if (lane >= o) x += v;
    }
    __shared__ int sh[32];
    if (lane == 31) sh[w] = x;
    __syncthreads();
    if (w == 0) {
        int y = sh[lane];
#pragma unroll
        for (int o = 1; o < 32; o <<= 1) {
            int v = __shfl_up_sync(0xffffffffu, y, o);
            if (lane >= o) y += v;
        }
        sh[lane] = y;
    }
    __syncthreads();
    int off = g_bsum[blk] + (x - tsum) + (w > 0 ? sh[w - 1] : 0);
    if (i + 0 < n) rs[i + 0] = off;
    if (i + 1 < n) rs[i + 1] = off + e1;
    if (i + 2 < n) rs[i + 2] = off + e2;
    if (i + 3 < n) rs[i + 3] = off + e3;
}

__global__ void k_scatter(const int* __restrict__ ei) {
    int p = blockIdx.x * blockDim.x + threadIdx.x;
    if (p < NNZ) {
        int node = ei[p], he = ei[NNZ + p];
        int pos = atomicAdd(&g_cur_n[node], 1);
        g_pn_he[g_rs_n[node] + pos] = he;
        int pos2 = atomicAdd(&g_cur_e[he], 1);
        int slot = g_rs_e[he] + pos2;
        g_pe_node[slot] = node;
        g_pe_pin[slot] = p;
    }
}

// ---------------- xl = h @ W1 + b1 ; s1 = xl . att[:64]  (warp per node) ----------------
__global__ void k_xl(const float* __restrict__ x, const float* __restrict__ fp,
                     const float* __restrict__ W1, const float* __restrict__ b1,
                     const float* __restrict__ att) {
    __shared__ float sW1[32 * 64];
    int tid = threadIdx.x;
    for (int v = tid; v < 32 * 64; v += 256) sW1[v] = W1[v];
    __syncthreads();
    int wid = tid >> 5, lane = tid & 31;
    int node = blockIdx.x * 8 + wid;
    float h;
    if (lane < 29)        h = x[node * 29 + lane];
    else if (lane == 29)  h = fp[node * 2 + 0];
    else if (lane == 30)  h = fp[node * 2 + 1];
    else                  h = (g_mcount[node] > 0) ? 1.f : 0.f;
    float a0 = b1[lane], a1 = b1[lane + 32];
#pragma unroll
    for (int k = 0; k < 32; k++) {
        float hk = __shfl_sync(0xffffffffu, h, k);
        a0 += hk * sW1[k * 64 + lane];
        a1 += hk * sW1[k * 64 + lane + 32];
    }
    g_xl[node * 64 + lane] = a0;
    g_xl[node * 64 + lane + 32] = a1;
    float p = a0 * att[lane] + a1 * att[lane + 32];
    p = warpSum(p);
    if (lane == 0) g_s1[node] = p;
}

// ---------------- hyperedge aggregation (warp per he) ----------------
__global__ void k_he(const float* __restrict__ pinf, const float* __restrict__ Wpin,
                     const float* __restrict__ att) {
    __shared__ float sWpin[4 * 64];
    int tid = threadIdx.x;
    for (int v = tid; v < 256; v += 256) sWpin[v] = Wpin[v];
    __syncthreads();
    int wid = tid >> 5, lane = tid & 31;
    int he = blockIdx.x * 8 + wid;
    int start = g_rs_e[he], end = g_rs_e[he + 1];
    int c0 = lane * 2;
    float acc0 = 0.f, acc1 = 0.f;
    float4 pfs = make_float4(0.f, 0.f, 0.f, 0.f);
    for (int s = start; s < end; s++) {
        int node = g_pe_node[s];
        int pin = g_pe_pin[s];
        float4 pf = *(const float4*)&pinf[pin * 4];   // broadcast across warp
        float2 xv = *(const float2*)&g_xl[node * 64 + c0];
        acc0 += xv.x; acc1 += xv.y;
        pfs.x += pf.x; pfs.y += pf.y; pfs.z += pf.z; pfs.w += pf.w;
    }
    acc0 += pfs.x * sWpin[c0]       + pfs.y * sWpin[64 + c0]
          + pfs.z * sWpin[128 + c0] + pfs.w * sWpin[192 + c0];
    acc1 += pfs.x * sWpin[c0 + 1]       + pfs.y * sWpin[64 + c0 + 1]
          + pfs.z * sWpin[128 + c0 + 1] + pfs.w * sWpin[192 + c0 + 1];
    int deg = end - start;
    float inv = 1.f / fmaxf((float)deg, 1.f);
    float e0 = acc0 * inv, e1 = acc1 * inv;
    *(float2*)&g_efeat[he * 64 + c0] = make_float2(e0, e1);
    float p = e0 * att[64 + c0] + e1 * att[64 + c0 + 1];
    p = warpSum(p);
    if (lane == 0) g_s2[he] = p;
}

// ---------------- node aggregation: softmax + PNA -> split fp16 (high occupancy) ----------------
__global__ void k_node() {
    int tid = threadIdx.x;
    int wid = tid >> 5, lane = tid & 31;
    int node = blockIdx.x * 8 + wid;
    int start = g_rs_n[node];
    int deg = g_rs_n[node + 1] - start;
    int c0 = lane * 2;
    float2 sum = make_float2(0.f, 0.f), sq = make_float2(0.f, 0.f);
    float2 vmx = make_float2(-INFINITY, -INFINITY);
    float2 vmn = make_float2(INFINITY, INFINITY);

    size_t base = (size_t)node * 256 + c0;
    if (deg == 0) {
        __half2 z = __floats2half2_rn(0.f, 0.f);
        __half2 zl = z;
        __half2 e, el;
        split2(1e-6f, 1e-6f, e, el);
        *(__half2*)&g_pAhi[base]       = z;  *(__half2*)&g_pAlo[base]       = zl;
        *(__half2*)&g_pAhi[base + 64]  = z;  *(__half2*)&g_pAlo[base + 64]  = zl;
        *(__half2*)&g_pAhi[base + 128] = z;  *(__half2*)&g_pAlo[base + 128] = zl;
        *(__half2*)&g_pAhi[base + 192] = e;  *(__half2*)&g_pAlo[base + 192] = el;
        return;
    }
    float s1n = g_s1[node];
    if (deg <= 32) {
        int he_l = 0; float a = -INFINITY;
        if (lane < deg) { he_l = g_pn_he[start + lane]; a = lrelu(s1n + g_s2[he_l]); }
        float m = warpMax(a);
        float ex = (lane < deg) ? expf(a - m) : 0.f;
        float den = warpSum(ex);
        float invden = 1.f / (den + 1e-16f);
        for (int j = 0; j < deg; j++) {
            float alpha = __shfl_sync(0xffffffffu, ex, j) * invden;
            int hej = __shfl_sync(0xffffffffu, he_l, j);
            float2 eg = *(const float2*)&g_efeat[hej * 64 + c0];
            float m0 = eg.x * alpha, m1 = eg.y * alpha;
            sum.x += m0; sum.y += m1;
            sq.x += m0 * m0; sq.y += m1 * m1;
            vmx.x = fmaxf(vmx.x, m0); vmx.y = fmaxf(vmx.y, m1);
            vmn.x = fminf(vmn.x, m0); vmn.y = fminf(vmn.y, m1);
        }
    } else {
        float lm = -INFINITY;
        for (int j = lane; j < deg; j += 32) {
            int he = g_pn_he[start + j];
            lm = fmaxf(lm, lrelu(s1n + g_s2[he]));
        }
        float m = warpMax(lm);
        float ls = 0.f;
        for (int j = lane; j < deg; j += 32) {
            int he = g_pn_he[start + j];
            ls += expf(lrelu(s1n + g_s2[he]) - m);
        }
        float den = warpSum(ls);
        float invden = 1.f / (den + 1e-16f);
        for (int j = 0; j < deg; j++) {
            int he = g_pn_he[start + j];
            float alpha = expf(lrelu(s1n + g_s2[he]) - m) * invden;
            float2 eg = *(const float2*)&g_efeat[he * 64 + c0];
            float m0 = eg.x * alpha, m1 = eg.y * alpha;
            sum.x += m0; sum.y += m1;
            sq.x += m0 * m0; sq.y += m1 * m1;
            vmx.x = fmaxf(vmx.x, m0); vmx.y = fmaxf(vmx.y, m1);
            vmn.x = fminf(vmn.x, m0); vmn.y = fminf(vmn.y, m1);
        }
    }
    float invd = 1.f / (float)deg;
    float2 mean = make_float2(sum.x * invd, sum.y * invd);
    float2 msq  = make_float2(sq.x * invd, sq.y * invd);
    float2 stdv = make_float2(sqrtf(fmaxf(msq.x - mean.x * mean.x, 0.f) + 1e-12f),
                              sqrtf(fmaxf(msq.y - mean.y * mean.y, 0.f) + 1e-12f));
    __half2 h, l;
    split2(mean.x, mean.y, h, l);
    *(__half2*)&g_pAhi[base] = h;       *(__half2*)&g_pAlo[base] = l;
    split2(vmx.x, vmx.y, h, l);
    *(__half2*)&g_pAhi[base + 64] = h;  *(__half2*)&g_pAlo[base + 64] = l;
    split2(vmn.x, vmn.y, h, l);
    *(__half2*)&g_pAhi[base + 128] = h; *(__half2*)&g_pAlo[base + 128] = l;
    split2(stdv.x, stdv.y, h, l);
    *(__half2*)&g_pAhi[base + 192] = h; *(__half2*)&g_pAlo[base + 192] = l;
}

// ---------------- split-fp16 mma.sync GEMM + fused pools (no hx writeback) ----------------
// D = Ahi*Bhi + Ahi*Blo + Alo*Bhi  (fp32 accumulate) ~ fp32 precision.
#define ASTR 264
#define BSTR 264
#define MMA_SMEM ((128 * ASTR * 2 + 64 * BSTR * 2) * 2 + 256)

__global__ __launch_bounds__(256, 1) void k_mma(const float* __restrict__ bpost) {
    extern __shared__ char smraw[];
    __half* sAh = (__half*)smraw;
    __half* sAl = sAh + 128 * ASTR;
    __half* sBh = sAl + 128 * ASTR;
    __half* sBl = sBh + 64 * BSTR;
    float* pool = (float*)(sBl + 64 * BSTR);
    int tid = threadIdx.x;
    int node0 = blockIdx.x * 128;
    if (tid < 64) pool[tid] = 0.f;

    // A: 128 rows x 256 fp16 (hi+lo); thread t: row=t/2, half-range=(t&1)*128
    {
        int row = tid >> 1, half = (tid & 1) * 128;
        size_t goff = (size_t)(node0 + row) * 256 + half;
        const __half* srch = &g_pAhi[goff];
        const __half* srcl = &g_pAlo[goff];
        __half* dsth = &sAh[row * ASTR + half];
        __half* dstl = &sAl[row * ASTR + half];
#pragma unroll
        for (int i = 0; i < 16; i++) {
            *(uint4*)&dsth[i * 8] = *(const uint4*)&srch[i * 8];
            *(uint4*)&dstl[i * 8] = *(const uint4*)&srcl[i * 8];
        }
    }
    // B: 64 n-rows x 256 k fp16 (hi+lo)
    {
        int n = tid >> 2, q = (tid & 3) * 64;
        const __half* srch = &g_whh[n * 256 + q];
        const __half* srcl = &g_whl[n * 256 + q];
        __half* dsth = &sBh[n * BSTR + q];
        __half* dstl = &sBl[n * BSTR + q];
#pragma unroll
        for (int i = 0; i < 8; i++) {
            *(uint4*)&dsth[i * 8] = *(const uint4*)&srch[i * 8];
            *(uint4*)&dstl[i * 8] = *(const uint4*)&srcl[i * 8];
        }
    }
    __syncthreads();

    int wid = tid >> 5, lane = tid & 31;
    int r0 = wid * 16;
    int g = lane >> 2, t4 = lane & 3;

    float acc[8][4];
#pragma unroll
    for (int i = 0; i < 8; i++)
#pragma unroll
        for (int j = 0; j < 4; j++) acc[i][j] = 0.f;

    unsigned aRow = (unsigned)((r0 + (lane & 15)) * ASTR + ((lane >> 4) << 3));
    unsigned aHiBase = smem_u32(sAh) + aRow * 2u;
    unsigned aLoBase = smem_u32(sAl) + aRow * 2u;
    unsigned bHiBase = smem_u32(sBh);
    unsigned bLoBase = smem_u32(sBl);

#pragma unroll
    for (int ks = 0; ks < 16; ks++) {
        int k0 = ks * 16;
        unsigned ah0, ah1, ah2, ah3, al0, al1, al2, al3;
        asm volatile("ldmatrix.sync.aligned.m8n8.x4.shared.b16 {%0,%1,%2,%3}, [%4];"
                     : "=r"(ah0), "=r"(ah1), "=r"(ah2), "=r"(ah3)
                     : "r"(aHiBase + (unsigned)(k0 * 2)));
        asm volatile("ldmatrix.sync.aligned.m8n8.x4.shared.b16 {%0,%1,%2,%3}, [%4];"
                     : "=r"(al0), "=r"(al1), "=r"(al2), "=r"(al3)
                     : "r"(aLoBase + (unsigned)(k0 * 2)));
#pragma unroll
        for (int nt = 0; nt < 8; nt++) {
            unsigned boff = (unsigned)(((nt * 8 + g) * BSTR + k0 + t4 * 2) * 2);
            unsigned bh0, bh1, bl0, bl1;
            asm volatile("ld.shared.b32 %0, [%1];" : "=r"(bh0) : "r"(bHiBase + boff));
            asm volatile("ld.shared.b32 %0, [%1];" : "=r"(bh1) : "r"(bHiBase + boff + 16u));
            asm volatile("ld.shared.b32 %0, [%1];" : "=r"(bl0) : "r"(bLoBase + boff));
            asm volatile("ld.shared.b32 %0, [%1];" : "=r"(bl1) : "r"(bLoBase + boff + 16u));
            asm volatile(
                "mma.sync.aligned.m16n8k16.row.col.f32.f16.f16.f32 "
                "{%0,%1,%2,%3}, {%4,%5,%6,%7}, {%8,%9}, {%0,%1,%2,%3};"
                : "+f"(acc[nt][0]), "+f"(acc[nt][1]), "+f"(acc[nt][2]), "+f"(acc[nt][3])
                : "r"(ah0), "r"(ah1), "r"(ah2), "r"(ah3), "r"(bh0), "r"(bh1));
            asm volatile(
                "mma.sync.aligned.m16n8k16.row.col.f32.f16.f16.f32 "
                "{%0,%1,%2,%3}, {%4,%5,%6,%7}, {%8,%9}, {%0,%1,%2,%3};"
                : "+f"(acc[nt][0]), "+f"(acc[nt][1]), "+f"(acc[nt][2]), "+f"(acc[nt][3])
                : "r"(ah0), "r"(ah1), "r"(ah2), "r"(ah3), "r"(bl0), "r"(bl1));
            asm volatile(
                "mma.sync.aligned.m16n8k16.row.col.f32.f16.f16.f32 "
                "{%0,%1,%2,%3}, {%4,%5,%6,%7}, {%8,%9}, {%0,%1,%2,%3};"
                : "+f"(acc[nt][0]), "+f"(acc[nt][1]), "+f"(acc[nt][2]), "+f"(acc[nt][3])
                : "r"(al0), "r"(al1), "r"(al2), "r"(al3), "r"(bh0), "r"(bh1));
        }
    }

    // epilogue: bias + lrelu; fused mean-pool (smem) + macro-pool (mcount-weighted)
    int row0 = node0 + r0 + g, row1 = row0 + 8;
    bool v0 = row0 < N_NODES, v1 = row1 < N_NODES;
    int cnt0 = v0 ? g_mcount[row0] : 0;
    int cnt1 = v1 ? g_mcount[row1] : 0;
#pragma unroll
    for (int nt = 0; nt < 8; nt++) {
        int c = nt * 8 + t4 * 2;
        float2 bp = *(const float2*)&bpost[c];
        float h00 = lrelu(acc[nt][0] + bp.x), h01 = lrelu(acc[nt][1] + bp.y);
        float h10 = lrelu(acc[nt][2] + bp.x), h11 = lrelu(acc[nt][3] + bp.y);
        if (cnt0) {
            atomicAdd(&g_pool_macro[c], (float)cnt0 * h00);
            atomicAdd(&g_pool_macro[c + 1], (float)cnt0 * h01);
        }
        if (cnt1) {
            atomicAdd(&g_pool_macro[c], (float)cnt1 * h10);
            atomicAdd(&g_pool_macro[c + 1], (float)cnt1 * h11);
        }
        float s0 = (v0 ? h00 : 0.f) + (v1 ? h10 : 0.f);
        float s1 = (v0 ? h01 : 0.f) + (v1 ? h11 : 0.f);
#pragma unroll
        for (int o = 4; o < 32; o <<= 1) {
            s0 += __shfl_xor_sync(0xffffffffu, s0, o);
            s1 += __shfl_xor_sync(0xffffffffu, s1, o);
        }
        if (g == 0) {
            atomicAdd(&pool[c], s0);
            atomicAdd(&pool[c + 1], s1);
        }
    }
    __syncthreads();
    if (tid < 64) atomicAdd(&g_pool_all[tid], pool[tid]);
}

// ---------------- MLP head ----------------
__global__ void k_mlp(const float* __restrict__ Wm1, const float* __restrict__ bm1,
                      const float* __restrict__ Wm2, const float* __restrict__ bm2,
                      const float* __restrict__ Wm3, const float* __restrict__ bm3,
                      float* __restrict__ out) {
    int t = threadIdx.x;
    __shared__ float pooled[128];
    __shared__ float z1[64];
    __shared__ float z2[32];
    if (t < 64) {
        pooled[t] = g_pool_macro[t] * (1.f / (float)N_MACRO);
        pooled[t + 64] = g_pool_all[t] * (1.f / (float)N_NODES);
    }
    __syncthreads();
    if (t < 64) {
        float a = bm1[t];
        for (int k = 0; k < 128; k++) a += pooled[k] * Wm1[k * 64 + t];
        z1[t] = lrelu(a);
    }
    __syncthreads();
    if (t < 32) {
        float a = bm2[t];
        for (int k = 0; k < 64; k++) a += z1[k] * Wm2[k * 32 + t];
        z2[t] = lrelu(a);
    }
    __syncthreads();
    if (t < 32) {
        float p = z2[t] * Wm3[t];
        p = warpSum(p);
        if (t == 0) out[0] = p + bm3[0];
    }
}

// ---------------- launch ----------------
extern "C" void kernel_launch(void* const* d_in, const int* in_sizes, int n_in,
                              void* d_out, int out_size) {
    const float* x     = (const float*)d_in[0];
    const float* fp    = (const float*)d_in[1];
    const int*   ei    = (const int*)d_in[2];
    const float* pinf  = (const float*)d_in[3];
    const int*   mi    = (const int*)d_in[4];
    const float* W1    = (const float*)d_in[5];
    const float* b1    = (const float*)d_in[6];
    const float* Wpin  = (const float*)d_in[7];
    const float* att   = (const float*)d_in[8];
    const float* Wpost = (const float*)d_in[9];
    const float* bpost = (const float*)d_in[10];
    const float* Wm1   = (const float*)d_in[11];
    const float* bm1   = (const float*)d_in[12];
    const float* Wm2   = (const float*)d_in[13];
    const float* bm2   = (const float*)d_in[14];
    const float* Wm3   = (const float*)d_in[15];
    const float* bm3   = (const float*)d_in[16];
    float* out = (float*)d_out;

    cudaFuncSetAttribute(k_mma, cudaFuncAttributeMaxDynamicSharedMemorySize, MMA_SMEM);

    k_init<<<400, 256>>>();
    k_prep<<<64, 256>>>(Wpost);
    k_ismacro<<<2, 256>>>(mi);
    k_deg<<<(NNZ + 255) / 256, 256>>>(ei);
    k_scan1<<<NBN + NBE, 1024>>>();
    k_scan2<<<1, 64>>>();
    k_scan3<<<NBN + NBE, 1024>>>();
    k_scatter<<<(NNZ + 255) / 256, 256>>>(ei);
    k_xl<<<N_NODES / 8, 256>>>(x, fp, W1, b1, att);
    k_he<<<N_HE / 8, 256>>>(pinf, Wpin, att);
    k_node<<<N_NODES / 8, 256>>>();
    k_mma<<<MMA_GRID, 256, MMA_SMEM>>>(bpost);
    k_mlp<<<1, 128>>>(Wm1, bm1, Wm2, bm2, Wm3, bm3, out);
}

// round 15
// speedup vs baseline: 1.2004x; 1.0431x over previous
#include <cuda_runtime.h>
#include <cuda_fp16.h>
#include <math.h>

#define N_NODES 200000
#define N_HE    100000
#define NNZ     1000000
#define N_MACRO 512
#define CC      64
#define SLOPE   0.1f

#define NBN 49   // ceil(200000/4096)
#define NBE 25   // ceil(100000/4096)

#define NN_PAD 200064          // 1563 * 128
#define MMA_GRID 1563

// ---------------- device scratch ----------------
__device__ float g_xl[N_NODES * CC];
__device__ float g_s1[N_NODES];
__device__ float g_efeat[N_HE * CC];
__device__ float g_s2[N_HE];
__device__ float g_pfe[N_HE * 4];
__device__ int   g_mcount[N_NODES];
__device__ int   g_deg_n[N_NODES];
__device__ int   g_deg_e[N_HE];
__device__ int   g_rs_n[N_NODES + 1];
__device__ int   g_rs_e[N_HE + 1];
__device__ int   g_cur_n[N_NODES];
__device__ int   g_cur_e[N_HE];
__device__ int   g_bsum[NBN + NBE];
__device__ int   g_pn_he[NNZ];
__device__ int   g_pe_node[NNZ];
__device__ __half g_pAhi[(size_t)NN_PAD * 256];   // 102.4 MB (pad rows stay 0)
__device__ __half g_pAlo[(size_t)NN_PAD * 256];   // 102.4 MB
__device__ __half g_whh[64 * 256];                // Wpost^T fp16 hi: [n][k]
__device__ __half g_whl[64 * 256];                // Wpost^T fp16 lo
__device__ float g_pool_all[CC];
__device__ float g_pool_macro[CC];

__device__ __forceinline__ float lrelu(float v) { return v >= 0.f ? v : SLOPE * v; }

__device__ __forceinline__ float warpMax(float v) {
#pragma unroll
    for (int o = 16; o > 0; o >>= 1) v = fmaxf(v, __shfl_xor_sync(0xffffffffu, v, o));
    return v;
}
__device__ __forceinline__ float warpSum(float v) {
#pragma unroll
    for (int o = 16; o > 0; o >>= 1) v += __shfl_xor_sync(0xffffffffu, v, o);
    return v;
}
__device__ __forceinline__ int warpSumI(int v) {
#pragma unroll
    for (int o = 16; o > 0; o >>= 1) v += __shfl_xor_sync(0xffffffffu, v, o);
    return v;
}
__device__ __forceinline__ unsigned smem_u32(const void* p) {
    unsigned a;
    asm("{ .reg .u64 t; cvta.to.shared.u64 t, %1; cvt.u32.u64 %0, t; }" : "=r"(a) : "l"(p));
    return a;
}
// split a float2 into fp16 hi pair + fp16 lo (residual) pair
__device__ __forceinline__ void split2(float vx, float vy, __half2& hi, __half2& lo) {
    __half hx = __float2half_rn(vx), hy = __float2half_rn(vy);
    __half lx = __float2half_rn(vx - __half2float(hx));
    __half ly = __float2half_rn(vy - __half2float(hy));
    hi = __halves2half2(hx, hy);
    lo = __halves2half2(lx, ly);
}

// ---------------- init / CSR build ----------------
__global__ void k_init() {
    int i = blockIdx.x * blockDim.x + threadIdx.x;
    int st = gridDim.x * blockDim.x;
    for (int j = i; j < N_NODES; j += st) { g_deg_n[j] = 0; g_cur_n[j] = 0; g_mcount[j] = 0; }
    for (int j = i; j < N_HE; j += st)    { g_deg_e[j] = 0; g_cur_e[j] = 0; }
    for (int j = i; j < N_HE * 4; j += st) g_pfe[j] = 0.f;
    if (i < CC) { g_pool_all[i] = 0.f; g_pool_macro[i] = 0.f; }
}

// Wpost [256 k][64 n] fp32 -> g_whh/g_whl [64 n][256 k] fp16 split (transposed)
__global__ void k_prep(const float* __restrict__ Wpost) {
    int i = blockIdx.x * blockDim.x + threadIdx.x;   // i = n*256 + k
    if (i < 64 * 256) {
        int n = i >> 8, k = i & 255;
        float w = Wpost[k * 64 + n];
        __half h = __float2half_rn(w);
        g_whh[i] = h;
        g_whl[i] = __float2half_rn(w - __half2float(h));
    }
}

__global__ void k_ismacro(const int* __restrict__ mi) {
    int i = blockIdx.x * blockDim.x + threadIdx.x;
    if (i < N_MACRO) atomicAdd(&g_mcount[mi[i]], 1);
}

__global__ void k_deg(const int* __restrict__ ei, const float* __restrict__ pinf) {
    int p = blockIdx.x * blockDim.x + threadIdx.x;
    if (p < NNZ) {
        int he = ei[NNZ + p];
        atomicAdd(&g_deg_n[ei[p]], 1);
        atomicAdd(&g_deg_e[he], 1);
        float4 pf = *(const float4*)&pinf[p * 4];
        atomicAdd(&g_pfe[he * 4 + 0], pf.x);
        atomicAdd(&g_pfe[he * 4 + 1], pf.y);
        atomicAdd(&g_pfe[he * 4 + 2], pf.z);
        atomicAdd(&g_pfe[he * 4 + 3], pf.w);
    }
}

// ----- 3-phase multi-block exclusive scan -----
__global__ void k_scan1() {
    int blk = blockIdx.x;
    const int* deg; int base; int n;
    if (blk < NBN) { deg = g_deg_n; base = blk * 4096; n = N_NODES; }
    else           { deg = g_deg_e; base = (blk - NBN) * 4096; n = N_HE; }
    int t = threadIdx.x;
    int i = base + t * 4;
    int s = 0;
    if (i + 3 < n) {
        int4 v = *(const int4*)&deg[i];
        s = v.x + v.y + v.z + v.w;
    } else {
        for (int j = 0; j < 4; j++) if (i + j < n) s += deg[i + j];
    }
    s = warpSumI(s);
    __shared__ int sh[32];
    int lane = t & 31, w = t >> 5;
    if (lane == 0) sh[w] = s;
    __syncthreads();
    if (w == 0) {
        int v = sh[lane];
        v = warpSumI(v);
        if (lane == 0) g_bsum[blk] = v;
    }
}

__global__ void k_scan2() {
    int t = threadIdx.x;
    if (t == 0) {
        int run = 0;
        for (int b = 0; b < NBN; b++) { int v = g_bsum[b]; g_bsum[b] = run; run += v; }
        g_rs_n[N_NODES] = NNZ;
    }
    if (t == 32) {
        int run = 0;
        for (int b = NBN; b < NBN + NBE; b++) { int v = g_bsum[b]; g_bsum[b] = run; run += v; }
        g_rs_e[N_HE] = NNZ;
    }
}

__global__ void k_scan3() {
    int blk = blockIdx.x;
    const int* deg; int* rs; int base; int n;
    if (blk < NBN) { deg = g_deg_n; rs = g_rs_n; base = blk * 4096; n = N_NODES; }
    else           { deg = g_deg_e; rs = g_rs_e; base = (blk - NBN) * 4096; n = N_HE; }
    int t = threadIdx.x;
    int lane = t & 31, w = t >> 5;
    int i = base + t * 4;
    int d0 = 0, d1 = 0, d2 = 0, d3 = 0;
    if (i + 3 < n) {
        int4 v = *(const int4*)&deg[i];
        d0 = v.x; d1 = v.y; d2 = v.z; d3 = v.w;
    } else {
        if (i + 0 < n) d0 = deg[i + 0];
        if (i + 1 < n) d1 = deg[i + 1];
        if (i + 2 < n) d2 = deg[i + 2];
        if (i + 3 < n) d3 = deg[i + 3];
    }
    int e1 = d0, e2 = d0 + d1, e3 = d0 + d1 + d2;
    int tsum = e3 + d3;
    int x = tsum;
#pragma unroll
    for (int o = 1; o < 32; o <<= 1) {
        int v = __shfl_up_sync(0xffffffffu, x, o);
        if (lane >= o) x += v;
    }
    __shared__ int sh[32];
    if (lane == 31) sh[w] = x;
    __syncthreads();
    if (w == 0) {
        int y = sh[lane];
#pragma unroll
        for (int o = 1; o < 32; o <<= 1) {
            int v = __shfl_up_sync(0xffffffffu, y, o);
            if (lane >= o) y += v;
        }
        sh[lane] = y;
    }
    __syncthreads();
    int off = g_bsum[blk] + (x - tsum) + (w > 0 ? sh[w - 1] : 0);
    if (i + 0 < n) rs[i + 0] = off;
    if (i + 1 < n) rs[i + 1] = off + e1;
    if (i + 2 < n) rs[i + 2] = off + e2;
    if (i + 3 < n) rs[i + 3] = off + e3;
}

__global__ void k_scatter(const int* __restrict__ ei) {
    int p = blockIdx.x * blockDim.x + threadIdx.x;
    if (p < NNZ) {
        int node = ei[p], he = ei[NNZ + p];
        int pos = atomicAdd(&g_cur_n[node], 1);
        g_pn_he[g_rs_n[node] + pos] = he;
        int pos2 = atomicAdd(&g_cur_e[he], 1);
        g_pe_node[g_rs_e[he] + pos2] = node;
    }
}

// ---------------- xl = h @ W1 + b1 ; s1 = xl . att[:64]  (warp per node) ----------------
__global__ void k_xl(const float* __restrict__ x, const float* __restrict__ fp,
                     const float* __restrict__ W1, const float* __restrict__ b1,
                     const float* __restrict__ att) {
    __shared__ float sW1[32 * 64];
    int tid = threadIdx.x;
    for (int v = tid; v < 32 * 64; v += 256) sW1[v] = W1[v];
    __syncthreads();
    int wid = tid >> 5, lane = tid & 31;
    int node = blockIdx.x * 8 + wid;
    float h;
    if (lane < 29)        h = x[node * 29 + lane];
    else if (lane == 29)  h = fp[node * 2 + 0];
    else if (lane == 30)  h = fp[node * 2 + 1];
    else                  h = (g_mcount[node] > 0) ? 1.f : 0.f;
    float a0 = b1[lane], a1 = b1[lane + 32];
#pragma unroll
    for (int k = 0; k < 32; k++) {
        float hk = __shfl_sync(0xffffffffu, h, k);
        a0 += hk * sW1[k * 64 + lane];
        a1 += hk * sW1[k * 64 + lane + 32];
    }
    g_xl[node * 64 + lane] = a0;
    g_xl[node * 64 + lane + 32] = a1;
    float p = a0 * att[lane] + a1 * att[lane + 32];
    p = warpSum(p);
    if (lane == 0) g_s1[node] = p;
}

// ---------------- hyperedge aggregation (warp per he, pfe presummed) ----------------
__global__ void k_he(const float* __restrict__ Wpin, const float* __restrict__ att) {
    __shared__ float sWpin[4 * 64];
    int tid = threadIdx.x;
    for (int v = tid; v < 256; v += 256) sWpin[v] = Wpin[v];
    __syncthreads();
    int wid = tid >> 5, lane = tid & 31;
    int he = blockIdx.x * 8 + wid;
    int start = g_rs_e[he], end = g_rs_e[he + 1];
    int c0 = lane * 2;
    float acc0 = 0.f, acc1 = 0.f;
    for (int s = start; s < end; s++) {
        int node = g_pe_node[s];
        float2 xv = *(const float2*)&g_xl[node * 64 + c0];
        acc0 += xv.x; acc1 += xv.y;
    }
    float4 pf = *(const float4*)&g_pfe[he * 4];
    acc0 += pf.x * sWpin[c0]       + pf.y * sWpin[64 + c0]
          + pf.z * sWpin[128 + c0] + pf.w * sWpin[192 + c0];
    acc1 += pf.x * sWpin[c0 + 1]       + pf.y * sWpin[64 + c0 + 1]
          + pf.z * sWpin[128 + c0 + 1] + pf.w * sWpin[192 + c0 + 1];
    int deg = end - start;
    float inv = 1.f / fmaxf((float)deg, 1.f);
    float e0 = acc0 * inv, e1 = acc1 * inv;
    *(float2*)&g_efeat[he * 64 + c0] = make_float2(e0, e1);
    float p = e0 * att[64 + c0] + e1 * att[64 + c0 + 1];
    p = warpSum(p);
    if (lane == 0) g_s2[he] = p;
}

// ---------------- node aggregation: softmax + PNA -> split fp16 (high occupancy) ----------------
__global__ void k_node() {
    int tid = threadIdx.x;
    int wid = tid >> 5, lane = tid & 31;
    int node = blockIdx.x * 8 + wid;
    int start = g_rs_n[node];
    int deg = g_rs_n[node + 1] - start;
    int c0 = lane * 2;
    float2 sum = make_float2(0.f, 0.f), sq = make_float2(0.f, 0.f);
    float2 vmx = make_float2(-INFINITY, -INFINITY);
    float2 vmn = make_float2(INFINITY, INFINITY);

    size_t base = (size_t)node * 256 + c0;
    if (deg == 0) {
        __half2 z = __floats2half2_rn(0.f, 0.f);
        __half2 zl = z;
        __half2 e, el;
        split2(1e-6f, 1e-6f, e, el);
        *(__half2*)&g_pAhi[base]       = z;  *(__half2*)&g_pAlo[base]       = zl;
        *(__half2*)&g_pAhi[base + 64]  = z;  *(__half2*)&g_pAlo[base + 64]  = zl;
        *(__half2*)&g_pAhi[base + 128] = z;  *(__half2*)&g_pAlo[base + 128] = zl;
        *(__half2*)&g_pAhi[base + 192] = e;  *(__half2*)&g_pAlo[base + 192] = el;
        return;
    }
    float s1n = g_s1[node];
    if (deg <= 32) {
        int he_l = 0; float a = -INFINITY;
        if (lane < deg) { he_l = g_pn_he[start + lane]; a = lrelu(s1n + g_s2[he_l]); }
        float m = warpMax(a);
        float ex = (lane < deg) ? expf(a - m) : 0.f;
        float den = warpSum(ex);
        float invden = 1.f / (den + 1e-16f);
        // batch-4 prefetch: decouple the 4 row gathers from the accumulation chain
        for (int j0 = 0; j0 < deg; j0 += 4) {
            int jn = deg - j0; if (jn > 4) jn = 4;
            float2 egb[4]; float alp[4];
#pragma unroll
            for (int u = 0; u < 4; u++) {
                int hej = __shfl_sync(0xffffffffu, he_l, (j0 + u) & 31);
                float av = __shfl_sync(0xffffffffu, ex, (j0 + u) & 31) * invden;
                if (u < jn) {
                    alp[u] = av;
                    egb[u] = *(const float2*)&g_efeat[hej * 64 + c0];
                }
            }
#pragma unroll
            for (int u = 0; u < 4; u++) {
                if (u < jn) {
                    float m0 = egb[u].x * alp[u], m1 = egb[u].y * alp[u];
                    sum.x += m0; sum.y += m1;
                    sq.x += m0 * m0; sq.y += m1 * m1;
                    vmx.x = fmaxf(vmx.x, m0); vmx.y = fmaxf(vmx.y, m1);
                    vmn.x = fminf(vmn.x, m0); vmn.y = fminf(vmn.y, m1);
                }
            }
        }
    } else {
        float lm = -INFINITY;
        for (int j = lane; j < deg; j += 32) {
            int he = g_pn_he[start + j];
            lm = fmaxf(lm, lrelu(s1n + g_s2[he]));
        }
        float m = warpMax(lm);
        float ls = 0.f;
        for (int j = lane; j < deg; j += 32) {
            int he = g_pn_he[start + j];
            ls += expf(lrelu(s1n + g_s2[he]) - m);
        }
        float den = warpSum(ls);
        float invden = 1.f / (den + 1e-16f);
        for (int j = 0; j < deg; j++) {
            int he = g_pn_he[start + j];
            float alpha = expf(lrelu(s1n + g_s2[he]) - m) * invden;
            float2 eg = *(const float2*)&g_efeat[he * 64 + c0];
            float m0 = eg.x * alpha, m1 = eg.y * alpha;
            sum.x += m0; sum.y += m1;
            sq.x += m0 * m0; sq.y += m1 * m1;
            vmx.x = fmaxf(vmx.x, m0); vmx.y = fmaxf(vmx.y, m1);
            vmn.x = fminf(vmn.x, m0); vmn.y = fminf(vmn.y, m1);
        }
    }
    float invd = 1.f / (float)deg;
    float2 mean = make_float2(sum.x * invd, sum.y * invd);
    float2 msq  = make_float2(sq.x * invd, sq.y * invd);
    float2 stdv = make_float2(sqrtf(fmaxf(msq.x - mean.x * mean.x, 0.f) + 1e-12f),
                              sqrtf(fmaxf(msq.y - mean.y * mean.y, 0.f) + 1e-12f));
    __half2 h, l;
    split2(mean.x, mean.y, h, l);
    *(__half2*)&g_pAhi[base] = h;       *(__half2*)&g_pAlo[base] = l;
    split2(vmx.x, vmx.y, h, l);
    *(__half2*)&g_pAhi[base + 64] = h;  *(__half2*)&g_pAlo[base + 64] = l;
    split2(vmn.x, vmn.y, h, l);
    *(__half2*)&g_pAhi[base + 128] = h; *(__half2*)&g_pAlo[base + 128] = l;
    split2(stdv.x, stdv.y, h, l);
    *(__half2*)&g_pAhi[base + 192] = h; *(__half2*)&g_pAlo[base + 192] = l;
}

// ---------------- split-fp16 mma.sync GEMM + fused pools (no hx writeback) ----------------
// D = Ahi*Bhi + Ahi*Blo + Alo*Bhi  (fp32 accumulate) ~ fp32 precision.
#define ASTR 264
#define BSTR 264
#define MMA_SMEM ((128 * ASTR * 2 + 64 * BSTR * 2) * 2 + 256)

__global__ __launch_bounds__(256, 1) void k_mma(const float* __restrict__ bpost) {
    extern __shared__ char smraw[];
    __half* sAh = (__half*)smraw;
    __half* sAl = sAh + 128 * ASTR;
    __half* sBh = sAl + 128 * ASTR;
    __half* sBl = sBh + 64 * BSTR;
    float* pool = (float*)(sBl + 64 * BSTR);
    int tid = threadIdx.x;
    int node0 = blockIdx.x * 128;
    if (tid < 64) pool[tid] = 0.f;

    // A: 128 rows x 256 fp16 (hi+lo); thread t: row=t/2, half-range=(t&1)*128
    {
        int row = tid >> 1, half = (tid & 1) * 128;
        size_t goff = (size_t)(node0 + row) * 256 + half;
        const __half* srch = &g_pAhi[goff];
        const __half* srcl = &g_pAlo[goff];
        __half* dsth = &sAh[row * ASTR + half];
        __half* dstl = &sAl[row * ASTR + half];
#pragma unroll
        for (int i = 0; i < 16; i++) {
            *(uint4*)&dsth[i * 8] = *(const uint4*)&srch[i * 8];
            *(uint4*)&dstl[i * 8] = *(const uint4*)&srcl[i * 8];
        }
    }
    // B: 64 n-rows x 256 k fp16 (hi+lo)
    {
        int n = tid >> 2, q = (tid & 3) * 64;
        const __half* srch = &g_whh[n * 256 + q];
        const __half* srcl = &g_whl[n * 256 + q];
        __half* dsth = &sBh[n * BSTR + q];
        __half* dstl = &sBl[n * BSTR + q];
#pragma unroll
        for (int i = 0; i < 8; i++) {
            *(uint4*)&dsth[i * 8] = *(const uint4*)&srch[i * 8];
            *(uint4*)&dstl[i * 8] = *(const uint4*)&srcl[i * 8];
        }
    }
    __syncthreads();

    int wid = tid >> 5, lane = tid & 31;
    int r0 = wid * 16;
    int g = lane >> 2, t4 = lane & 3;

    float acc[8][4];
#pragma unroll
    for (int i = 0; i < 8; i++)
#pragma unroll
        for (int j = 0; j < 4; j++) acc[i][j] = 0.f;

    unsigned aRow = (unsigned)((r0 + (lane & 15)) * ASTR + ((lane >> 4) << 3));
    unsigned aHiBase = smem_u32(sAh) + aRow * 2u;
    unsigned aLoBase = smem_u32(sAl) + aRow * 2u;
    unsigned bHiBase = smem_u32(sBh);
    unsigned bLoBase = smem_u32(sBl);

#pragma unroll
    for (int ks = 0; ks < 16; ks++) {
        int k0 = ks * 16;
        unsigned ah0, ah1, ah2, ah3, al0, al1, al2, al3;
        asm volatile("ldmatrix.sync.aligned.m8n8.x4.shared.b16 {%0,%1,%2,%3}, [%4];"
                     : "=r"(ah0), "=r"(ah1), "=r"(ah2), "=r"(ah3)
                     : "r"(aHiBase + (unsigned)(k0 * 2)));
        asm volatile("ldmatrix.sync.aligned.m8n8.x4.shared.b16 {%0,%1,%2,%3}, [%4];"
                     : "=r"(al0), "=r"(al1), "=r"(al2), "=r"(al3)
                     : "r"(aLoBase + (unsigned)(k0 * 2)));
#pragma unroll
        for (int nt = 0; nt < 8; nt++) {
            unsigned boff = (unsigned)(((nt * 8 + g) * BSTR + k0 + t4 * 2) * 2);
            unsigned bh0, bh1, bl0, bl1;
            asm volatile("ld.shared.b32 %0, [%1];" : "=r"(bh0) : "r"(bHiBase + boff));
            asm volatile("ld.shared.b32 %0, [%1];" : "=r"(bh1) : "r"(bHiBase + boff + 16u));
            asm volatile("ld.shared.b32 %0, [%1];" : "=r"(bl0) : "r"(bLoBase + boff));
            asm volatile("ld.shared.b32 %0, [%1];" : "=r"(bl1) : "r"(bLoBase + boff + 16u));
            asm volatile(
                "mma.sync.aligned.m16n8k16.row.col.f32.f16.f16.f32 "
                "{%0,%1,%2,%3}, {%4,%5,%6,%7}, {%8,%9}, {%0,%1,%2,%3};"
                : "+f"(acc[nt][0]), "+f"(acc[nt][1]), "+f"(acc[nt][2]), "+f"(acc[nt][3])
                : "r"(ah0), "r"(ah1), "r"(ah2), "r"(ah3), "r"(bh0), "r"(bh1));
            asm volatile(
                "mma.sync.aligned.m16n8k16.row.col.f32.f16.f16.f32 "
                "{%0,%1,%2,%3}, {%4,%5,%6,%7}, {%8,%9}, {%0,%1,%2,%3};"
                : "+f"(acc[nt][0]), "+f"(acc[nt][1]), "+f"(acc[nt][2]), "+f"(acc[nt][3])
                : "r"(ah0), "r"(ah1), "r"(ah2), "r"(ah3), "r"(bl0), "r"(bl1));
            asm volatile(
                "mma.sync.aligned.m16n8k16.row.col.f32.f16.f16.f32 "
                "{%0,%1,%2,%3}, {%4,%5,%6,%7}, {%8,%9}, {%0,%1,%2,%3};"
                : "+f"(acc[nt][0]), "+f"(acc[nt][1]), "+f"(acc[nt][2]), "+f"(acc[nt][3])
                : "r"(al0), "r"(al1), "r"(al2), "r"(al3), "r"(bh0), "r"(bh1));
        }
    }

    // epilogue: bias + lrelu; fused mean-pool (smem) + macro-pool (mcount-weighted)
    int row0 = node0 + r0 + g, row1 = row0 + 8;
    bool v0 = row0 < N_NODES, v1 = row1 < N_NODES;
    int cnt0 = v0 ? g_mcount[row0] : 0;
    int cnt1 = v1 ? g_mcount[row1] : 0;
#pragma unroll
    for (int nt = 0; nt < 8; nt++) {
        int c = nt * 8 + t4 * 2;
        float2 bp = *(const float2*)&bpost[c];
        float h00 = lrelu(acc[nt][0] + bp.x), h01 = lrelu(acc[nt][1] + bp.y);
        float h10 = lrelu(acc[nt][2] + bp.x), h11 = lrelu(acc[nt][3] + bp.y);
        if (cnt0) {
            atomicAdd(&g_pool_macro[c], (float)cnt0 * h00);
            atomicAdd(&g_pool_macro[c + 1], (float)cnt0 * h01);
        }
        if (cnt1) {
            atomicAdd(&g_pool_macro[c], (float)cnt1 * h10);
            atomicAdd(&g_pool_macro[c + 1], (float)cnt1 * h11);
        }
        float s0 = (v0 ? h00 : 0.f) + (v1 ? h10 : 0.f);
        float s1 = (v0 ? h01 : 0.f) + (v1 ? h11 : 0.f);
#pragma unroll
        for (int o = 4; o < 32; o <<= 1) {
            s0 += __shfl_xor_sync(0xffffffffu, s0, o);
            s1 += __shfl_xor_sync(0xffffffffu, s1, o);
        }
        if (g == 0) {
            atomicAdd(&pool[c], s0);
            atomicAdd(&pool[c + 1], s1);
        }
    }
    __syncthreads();
    if (tid < 64) atomicAdd(&g_pool_all[tid], pool[tid]);
}

// ---------------- MLP head ----------------
__global__ void k_mlp(const float* __restrict__ Wm1, const float* __restrict__ bm1,
                      const float* __restrict__ Wm2, const float* __restrict__ bm2,
                      const float* __restrict__ Wm3, const float* __restrict__ bm3,
                      float* __restrict__ out) {
    int t = threadIdx.x;
    __shared__ float pooled[128];
    __shared__ float z1[64];
    __shared__ float z2[32];
    if (t < 64) {
        pooled[t] = g_pool_macro[t] * (1.f / (float)N_MACRO);
        pooled[t + 64] = g_pool_all[t] * (1.f / (float)N_NODES);
    }
    __syncthreads();
    if (t < 64) {
        float a = bm1[t];
        for (int k = 0; k < 128; k++) a += pooled[k] * Wm1[k * 64 + t];
        z1[t] = lrelu(a);
    }
    __syncthreads();
    if (t < 32) {
        float a = bm2[t];
        for (int k = 0; k < 64; k++) a += z1[k] * Wm2[k * 32 + t];
        z2[t] = lrelu(a);
    }
    __syncthreads();
    if (t < 32) {
        float p = z2[t] * Wm3[t];
        p = warpSum(p);
        if (t == 0) out[0] = p + bm3[0];
    }
}

// ---------------- launch ----------------
extern "C" void kernel_launch(void* const* d_in, const int* in_sizes, int n_in,
                              void* d_out, int out_size) {
    const float* x     = (const float*)d_in[0];
    const float* fp    = (const float*)d_in[1];
    const int*   ei    = (const int*)d_in[2];
    const float* pinf  = (const float*)d_in[3];
    const int*   mi    = (const int*)d_in[4];
    const float* W1    = (const float*)d_in[5];
    const float* b1    = (const float*)d_in[6];
    const float* Wpin  = (const float*)d_in[7];
    const float* att   = (const float*)d_in[8];
    const float* Wpost = (const float*)d_in[9];
    const float* bpost = (const float*)d_in[10];
    const float* Wm1   = (const float*)d_in[11];
    const float* bm1   = (const float*)d_in[12];
    const float* Wm2   = (const float*)d_in[13];
    const float* bm2   = (const float*)d_in[14];
    const float* Wm3   = (const float*)d_in[15];
    const float* bm3   = (const float*)d_in[16];
    float* out = (float*)d_out;

    cudaFuncSetAttribute(k_mma, cudaFuncAttributeMaxDynamicSharedMemorySize, MMA_SMEM);

    k_init<<<400, 256>>>();
    k_prep<<<64, 256>>>(Wpost);
    k_ismacro<<<2, 256>>>(mi);
    k_deg<<<(NNZ + 255) / 256, 256>>>(ei, pinf);
    k_scan1<<<NBN + NBE, 1024>>>();
    k_scan2<<<1, 64>>>();
    k_scan3<<<NBN + NBE, 1024>>>();
    k_scatter<<<(NNZ + 255) / 256, 256>>>(ei);
    k_xl<<<N_NODES / 8, 256>>>(x, fp, W1, b1, att);
    k_he<<<N_HE / 8, 256>>>(Wpin, att);
    k_node<<<N_NODES / 8, 256>>>();
    k_mma<<<MMA_GRID, 256, MMA_SMEM>>>(bpost);
    k_mlp<<<1, 128>>>(Wm1, bm1, Wm2, bm2, Wm3, bm3, out);
}